// round 11
// baseline (speedup 1.0000x reference)
#include <cuda_runtime.h>
#include <cstdint>

#define NN 50000
#define DD 64
#define EE 800000
#define SCAN_BS 1024
#define NBLK ((NN + SCAN_BS - 1) / SCAN_BS)   // 49

// Scratch (no cudaMalloc allowed)
__device__ float g_AGG[NN * DD];     // reused for both aggregation passes
__device__ float g_H[NN * DD];
__device__ int   g_counts[NN];
__device__ int   g_cursor[NN];
__device__ int2  g_ofscnt[NN];       // (offset, count) packed for gather
__device__ int   g_offsets_tmp[NN];  // block-local exclusive offsets (scan1)
__device__ int   g_bsum[64];
__device__ int2  g_recs[EE];         // (src, bitcast(weight)) binned by dst

// ---------------------------------------------------------------------------
// edge_index dtype is ambiguous (jnp.int64 without x64 -> int32); detect at
// runtime: int64 values < 50000 have all-zero odd 32-bit words.
// ---------------------------------------------------------------------------
__device__ __forceinline__ bool detect_i64(const int* __restrict__ ei32) {
    return (ei32[1] | ei32[3] | ei32[5] | ei32[7] |
            ei32[9] | ei32[11] | ei32[13] | ei32[15]) == 0;
}

// ---------------------------------------------------------------------------
__global__ __launch_bounds__(256) void zero_counts_kernel() {
    int i = blockIdx.x * blockDim.x + threadIdx.x;
    if (i < NN) g_counts[i] = 0;
}

// 2 edges per thread, vectorized index loads.
__global__ __launch_bounds__(256) void hist_kernel(const int* __restrict__ ei32) {
    int t = blockIdx.x * blockDim.x + threadIdx.x;
    if (t >= EE / 2) return;
    bool is64 = detect_i64(ei32);
    int d0, d1;
    if (is64) {
        const longlong2* p = (const longlong2*)(ei32 + 2 * EE);
        longlong2 v = p[t];
        d0 = (int)v.x; d1 = (int)v.y;
    } else {
        const int2* p = (const int2*)(ei32 + EE);
        int2 v = p[t];
        d0 = v.x; d1 = v.y;
    }
    atomicAdd(&g_counts[d0], 1);
    atomicAdd(&g_counts[d1], 1);
}

// Block-wide inclusive scan (Hillis-Steele): block-exclusive offsets + block sums.
__global__ __launch_bounds__(SCAN_BS) void scan1_kernel() {
    __shared__ int s[SCAN_BS];
    int i = blockIdx.x * SCAN_BS + threadIdx.x;
    int v = (i < NN) ? g_counts[i] : 0;
    s[threadIdx.x] = v;
    __syncthreads();
#pragma unroll
    for (int off = 1; off < SCAN_BS; off <<= 1) {
        int y = (threadIdx.x >= off) ? s[threadIdx.x - off] : 0;
        __syncthreads();
        s[threadIdx.x] += y;
        __syncthreads();
    }
    if (i < NN) g_offsets_tmp[i] = s[threadIdx.x] - v;   // exclusive within block
    if (threadIdx.x == SCAN_BS - 1) g_bsum[blockIdx.x] = s[SCAN_BS - 1];
}

// Apply cross-block prefix (fused former scan2): each block computes
// prefix = sum(bsum[0..sb-1]) with a masked parallel load + warp shfl-reduce
// (NO serial gmem loop: ~one load latency total). sb = blockIdx>>2 is uniform
// per block since 256 | 1024.
__global__ __launch_bounds__(256) void scan3_kernel() {
    __shared__ int s_prefix;
    int lane = threadIdx.x & 31;
    if (threadIdx.x < 32) {
        int sb = blockIdx.x >> 2;
        int v = (lane < sb && lane < NBLK) ? g_bsum[lane] : 0;
        if (lane + 32 < sb && lane + 32 < NBLK) v += g_bsum[lane + 32];
#pragma unroll
        for (int off = 16; off > 0; off >>= 1)
            v += __shfl_xor_sync(0xffffffffu, v, off);
        if (lane == 0) s_prefix = v;
    }
    __syncthreads();
    int i = blockIdx.x * blockDim.x + threadIdx.x;
    if (i < NN) {
        int o = g_offsets_tmp[i] + s_prefix;
        int c = g_counts[i];
        g_ofscnt[i] = make_int2(o, c);
        g_cursor[i] = o;
    }
}

// 2 edges per thread, vectorized loads.
__global__ __launch_bounds__(256) void fill_kernel(const int* __restrict__ ei32,
                                                   const float* __restrict__ ew) {
    int t = blockIdx.x * blockDim.x + threadIdx.x;
    if (t >= EE / 2) return;
    bool is64 = detect_i64(ei32);
    int s0, s1, d0, d1;
    if (is64) {
        const longlong2* ps = (const longlong2*)ei32;
        const longlong2* pd = (const longlong2*)(ei32 + 2 * EE);
        longlong2 vs = ps[t];
        longlong2 vd = pd[t];
        s0 = (int)vs.x; s1 = (int)vs.y;
        d0 = (int)vd.x; d1 = (int)vd.y;
    } else {
        const int2* ps = (const int2*)ei32;
        const int2* pd = (const int2*)(ei32 + EE);
        int2 vs = ps[t];
        int2 vd = pd[t];
        s0 = vs.x; s1 = vs.y;
        d0 = vd.x; d1 = vd.y;
    }
    float2 w = ((const float2*)ew)[t];
    int p0 = atomicAdd(&g_cursor[d0], 1);
    g_recs[p0] = make_int2(s0, __float_as_int(w.x));
    int p1 = atomicAdd(&g_cursor[d1], 1);
    g_recs[p1] = make_int2(s1, __float_as_int(w.y));
}

// ---------------------------------------------------------------------------
// Gather: one warp per destination node, no atomics.
// Half-warps process edges pairwise, unrolled x2 (4 edges in flight per warp)
// to raise MLP against L2 latency; lane j<16 owns float4 j of the row.
// ---------------------------------------------------------------------------
__global__ __launch_bounds__(256) void gather_kernel(const float4* __restrict__ Xv,
                                                     float4* __restrict__ agg) {
    int warp = (blockIdx.x * blockDim.x + threadIdx.x) >> 5;
    if (warp >= NN) return;
    int lane = threadIdx.x & 31;
    int half = lane >> 4;
    int j    = lane & 15;

    int2 oc   = g_ofscnt[warp];      // lane-uniform single load
    int start = oc.x;
    int cnt   = oc.y;

    float4 acc = make_float4(0.f, 0.f, 0.f, 0.f);
    int i = half;
    for (; i + 2 < cnt; i += 4) {
        int2  rec0 = g_recs[start + i];
        int2  rec1 = g_recs[start + i + 2];
        float4 x0  = Xv[rec0.x * 16 + j];
        float4 x1  = Xv[rec1.x * 16 + j];
        float w0   = __int_as_float(rec0.y);
        float w1   = __int_as_float(rec1.y);
        acc.x += x0.x * w0;  acc.y += x0.y * w0;
        acc.z += x0.z * w0;  acc.w += x0.w * w0;
        acc.x += x1.x * w1;  acc.y += x1.y * w1;
        acc.z += x1.z * w1;  acc.w += x1.w * w1;
    }
    if (i < cnt) {
        int2  rec = g_recs[start + i];
        float w   = __int_as_float(rec.y);
        float4 x  = Xv[rec.x * 16 + j];
        acc.x += x.x * w;  acc.y += x.y * w;
        acc.z += x.z * w;  acc.w += x.w * w;
    }
    acc.x += __shfl_down_sync(0xffffffffu, acc.x, 16);
    acc.y += __shfl_down_sync(0xffffffffu, acc.y, 16);
    acc.z += __shfl_down_sync(0xffffffffu, acc.z, 16);
    acc.w += __shfl_down_sync(0xffffffffu, acc.w, 16);
    if (half == 0) agg[warp * 16 + j] = acc;
}

// ---------------------------------------------------------------------------
// Fused dual-GEMM + bias + sigmoid (scalar version — measured good).
//   out = sigmoid(A @ Wrel^T + R @ Wroot^T + bias)
// 128 threads, 64-row tile. Thread (cg = tid&7, rg = tid>>3) computes
// 8 cols {cg*8+i} x 4 rows {rg*4+t}. A/R read straight from gmem (8
// same-address lanes coalesce; no cross-warp reuse exists). Weights in smem
// with 8x8 slot transpose so per-instruction LDS addresses are contiguous
// 128B (conflict-free): slot = kq*64 + (c&7)*8 + (c>>3).
// ---------------------------------------------------------------------------
__global__ __launch_bounds__(128) void gemm_bias_sigmoid_kernel(
    const float* __restrict__ A,
    const float* __restrict__ R,
    const float* __restrict__ Wrel,   // [64,64] row-major [out][in]
    const float* __restrict__ Wroot,
    const float* __restrict__ b0, const float* __restrict__ b1,
    const float* __restrict__ b2, const float* __restrict__ b3,
    float* __restrict__ out)
{
    __shared__ float4 WrS[16 * 64];   // 16KB
    __shared__ float4 WoS[16 * 64];

    int tid = threadIdx.x;
    const float4* Wrel4  = (const float4*)Wrel;
    const float4* Wroot4 = (const float4*)Wroot;
    for (int idx = tid; idx < 1024; idx += 128) {
        int c = idx >> 4, kq = idx & 15;
        int slot = kq * 64 + (c & 7) * 8 + (c >> 3);
        WrS[slot] = Wrel4[idx];
        WoS[slot] = Wroot4[idx];
    }
    __syncthreads();

    int cg = tid & 7;
    int rg = tid >> 3;
    int row0 = blockIdx.x * 64 + rg * 4;

    float acc[8][4];
#pragma unroll
    for (int i = 0; i < 8; i++)
#pragma unroll
        for (int t = 0; t < 4; t++) acc[i][t] = 0.f;

    const float4* A4 = (const float4*)A;
    const float4* R4 = (const float4*)R;
    bool full = (row0 + 3 < NN);

#pragma unroll 2
    for (int kq = 0; kq < 16; kq++) {
        float4 a[4], r[4];
#pragma unroll
        for (int t = 0; t < 4; t++) {
            int row = row0 + t;
            if (full || row < NN) {
                a[t] = A4[row * 16 + kq];
                r[t] = R4[row * 16 + kq];
            } else {
                a[t] = make_float4(0.f, 0.f, 0.f, 0.f);
                r[t] = make_float4(0.f, 0.f, 0.f, 0.f);
            }
        }
#pragma unroll
        for (int i = 0; i < 8; i++) {
            float4 wr = WrS[kq * 64 + i * 8 + cg];   // lanes cg=0..7 contiguous
            float4 wo = WoS[kq * 64 + i * 8 + cg];
#pragma unroll
            for (int t = 0; t < 4; t++) {
                acc[i][t] += a[t].x * wr.x + a[t].y * wr.y
                           + a[t].z * wr.z + a[t].w * wr.w
                           + r[t].x * wo.x + r[t].y * wo.y
                           + r[t].z * wo.z + r[t].w * wo.w;
            }
        }
    }

    float bias[8];
#pragma unroll
    for (int i = 0; i < 8; i++) {
        int c = cg * 8 + i;
        bias[i] = b0[c] + b1[c];
        if (b2 != nullptr) bias[i] += b2[c] + b3[c];
    }

#pragma unroll
    for (int t = 0; t < 4; t++) {
        int row = row0 + t;
        if (row < NN) {
            float4 o0, o1;
            o0.x = 1.f / (1.f + __expf(-(acc[0][t] + bias[0])));
            o0.y = 1.f / (1.f + __expf(-(acc[1][t] + bias[1])));
            o0.z = 1.f / (1.f + __expf(-(acc[2][t] + bias[2])));
            o0.w = 1.f / (1.f + __expf(-(acc[3][t] + bias[3])));
            o1.x = 1.f / (1.f + __expf(-(acc[4][t] + bias[4])));
            o1.y = 1.f / (1.f + __expf(-(acc[5][t] + bias[5])));
            o1.z = 1.f / (1.f + __expf(-(acc[6][t] + bias[6])));
            o1.w = 1.f / (1.f + __expf(-(acc[7][t] + bias[7])));
            float4* op = (float4*)&out[row * DD + cg * 8];
            op[0] = o0;
            op[1] = o1;
        }
    }
}

// ---------------------------------------------------------------------------
extern "C" void kernel_launch(void* const* d_in, const int* in_sizes, int n_in,
                              void* d_out, int out_size)
{
    const float* X      = (const float*)d_in[0];
    const int*   ei     = (const int*)  d_in[1];   // raw; dtype auto-detected
    const float* ew     = (const float*)d_in[2];
    const float* Wrel1  = (const float*)d_in[3];
    const float* brel1  = (const float*)d_in[4];
    const float* Wroot1 = (const float*)d_in[5];
    const float* broot1 = (const float*)d_in[6];
    const float* brel2  = (const float*)d_in[8];
    const float* broot2 = (const float*)d_in[10];
    const float* Wrel3  = (const float*)d_in[11];
    const float* brel3  = (const float*)d_in[12];
    const float* Wroot3 = (const float*)d_in[13];
    const float* broot3 = (const float*)d_in[14];
    float* out = (float*)d_out;

    float *agg, *h;
    cudaGetSymbolAddress((void**)&agg, g_AGG);
    cudaGetSymbolAddress((void**)&h,   g_H);

    // --- CSR build (once; shared by both aggregation passes) ---
    zero_counts_kernel<<<(NN + 255) / 256, 256>>>();
    hist_kernel<<<(EE / 2 + 255) / 256, 256>>>(ei);
    scan1_kernel<<<NBLK, SCAN_BS>>>();
    scan3_kernel<<<(NN + 255) / 256, 256>>>();
    fill_kernel<<<(EE / 2 + 255) / 256, 256>>>(ei, ew);

    // --- pass 1: AGG = scatter(X[src]*w -> dst), atomic-free gather ---
    gather_kernel<<<(NN * 32 + 255) / 256, 256>>>((const float4*)X, (float4*)agg);

    // H = sigmoid(AGG@Wrel1^T + X@Wroot1^T + brel1+broot1+brel2+broot2)
    gemm_bias_sigmoid_kernel<<<(NN + 63) / 64, 128>>>(
        agg, X, Wrel1, Wroot1, brel1, broot1, brel2, broot2, h);

    // --- pass 2: AGG = scatter(H[src]*w -> dst) ---
    gather_kernel<<<(NN * 32 + 255) / 256, 256>>>((const float4*)h, (float4*)agg);

    // out = sigmoid(AGG@Wrel3^T + H@Wroot3^T + brel3+broot3)
    gemm_bias_sigmoid_kernel<<<(NN + 63) / 64, 128>>>(
        agg, h, Wrel3, Wroot3, brel3, broot3, nullptr, nullptr, out);
}